// round 13
// baseline (speedup 1.0000x reference)
#include <cuda_runtime.h>
#include <cuda_fp16.h>
#include <mma.h>
#include <cstdint>
#include <cstddef>

#define N_USERS 60000
#define N_ITEMS 40000
#define NTOT    100000
#define EMB     64
#define NNZ_C   2560000
#define BATCH   4096
#define NLAYERS 3
#define ELL_CAP 64         // deg ~ Poisson(25.6); P(deg>64) ~ 1e-14 per row

#define ROWS_PB 64         // rows per block in the fused layer kernel
#define LTHREADS 1024      // 64 rows x 16 lanes

// Scratch (__device__ globals; no allocation allowed)
__device__ __half2 g_egoh[2][(size_t)NTOT * (EMB / 2)]; // ping-pong fp16 ego
__device__ float   g_outs[4][(size_t)NTOT * EMB];       // slice 0 unused
__device__ float2  g_edges[(size_t)NTOT * ELL_CAP];     // (w as half2-bits, col), ELL
__device__ int     g_deg  [NTOT];
__device__ __half  g_wh [NLAYERS * 128 * 64];           // W' = [Wgc;Wbi] fp16 per layer
__device__ float   g_bs [NLAYERS * 64];                 // bgc + bbi per layer

__device__ __forceinline__ unsigned int h2_bits(__half2 v) {
    return *reinterpret_cast<unsigned int*>(&v);
}
__device__ __forceinline__ __half2 bits_h2(unsigned int b) {
    return *reinterpret_cast<__half2*>(&b);
}

// ---------------------------------------------------------------------------
// 0) One-time weight conversion: W' fp16 + summed bias
// ---------------------------------------------------------------------------
__global__ void prep_w_kernel(const float* __restrict__ Wgc,
                              const float* __restrict__ Wbi,
                              const float* __restrict__ bgc,
                              const float* __restrict__ bbi)
{
    int i = blockIdx.x * blockDim.x + threadIdx.x;
    if (i < NLAYERS * 128 * 64) {
        int k = i / 8192, rem = i - k * 8192;
        int kk = rem >> 6, n = rem & 63;
        float w = (kk < 64) ? Wgc[k * 4096 + kk * 64 + n]
                            : Wbi[k * 4096 + (kk - 64) * 64 + n];
        g_wh[i] = __float2half_rn(w);
    }
    if (i < NLAYERS * 64)
        g_bs[i] = bgc[i] + bbi[i];
}

// ---------------------------------------------------------------------------
// 1) masked ego -> fp16 egoh[0] only (slice 0 reconstructed in gather)
// ---------------------------------------------------------------------------
__global__ void init_kernel(const float4* __restrict__ ue,
                            const float4* __restrict__ ie,
                            const int* __restrict__ usz,
                            const int* __restrict__ isz)
{
    int i = blockIdx.x * blockDim.x + threadIdx.x;   // NTOT * 16 float4s
    if (i >= NTOT * 16) return;
    int r = i >> 4;
    int q = i & 15;
    int c0 = q * 4;
    float4 v; int sz;
    if (r < N_USERS) { v = ue[i];                              sz = usz[r]; }
    else             { v = ie[(size_t)(r - N_USERS) * 16 + q]; sz = isz[r - N_USERS]; }
    if (c0 + 0 >= sz) v.x = 0.f;
    if (c0 + 1 >= sz) v.y = 0.f;
    if (c0 + 2 >= sz) v.z = 0.f;
    if (c0 + 3 >= sz) v.w = 0.f;
    uint2 h;
    h.x = h2_bits(__floats2half2_rn(v.x, v.y));
    h.y = h2_bits(__floats2half2_rn(v.z, v.w));
    *reinterpret_cast<uint2*>(&g_egoh[0][(size_t)i * 2]) = h;
}

// ---------------------------------------------------------------------------
// 2) ELL scatter; edge record = (w as broadcast half2 bits, col bits)
// ---------------------------------------------------------------------------
__global__ void scatter_kernel(const float4* __restrict__ vals4,
                               const int4*   __restrict__ rows4,
                               const int4*   __restrict__ cols4)
{
    int i = blockIdx.x * blockDim.x + threadIdx.x;   // NNZ/4 threads
    if (i >= NNZ_C / 4) return;
    float4 v = vals4[i];
    int4   r = rows4[i];
    int4   c = cols4[i];

    #define PUT(vv, rr, cc) do {                                              \
        int p = atomicAdd(&g_deg[rr], 1);                                     \
        if (p < ELL_CAP) {                                                    \
            unsigned int wb = h2_bits(__float2half2_rn(vv));                  \
            g_edges[(size_t)(rr) * ELL_CAP + p] =                             \
                make_float2(__uint_as_float(wb), __int_as_float(cc));         \
        }                                                                     \
    } while (0)
    PUT(v.x, r.x, c.x);
    PUT(v.y, r.y, c.y);
    PUT(v.z, r.z, c.z);
    PUT(v.w, r.w, c.w);
    #undef PUT
}

// ---------------------------------------------------------------------------
// 3) Fused layer kernel: ELL SpMM (fp16 gather, HFMA2 chunk accum, fp32 flush)
//    -> A' in shared -> WMMA (64x64 out, K=128) -> bias/leakyReLU/norm.
//    Block: 1024 threads = 64 rows x 16 lanes = 32 warps (warps 0-15 do MMA).
// ---------------------------------------------------------------------------
__device__ __forceinline__ void accum_f(float4& acc, float wv, uint2 u)
{
    float2 f0 = __half22float2(bits_h2(u.x));
    float2 f1 = __half22float2(bits_h2(u.y));
    acc.x += wv * f0.x;
    acc.y += wv * f0.y;
    acc.z += wv * f1.x;
    acc.w += wv * f1.y;
}

#define A_LD   136   // 128 + 8 halves
#define W_LD   72    // 64 + 8 halves
#define A_BYTES (ROWS_PB * A_LD * 2)   // 17408
#define W_BYTES (128 * W_LD * 2)       // 18432

__global__ void __launch_bounds__(LTHREADS) layer_kernel(
    const __half*  __restrict__ Wh,     const float* __restrict__ bias,
    const __half2* __restrict__ ego_in, __half2* __restrict__ ego_out,
    float* __restrict__ norm_out,       int write_ego)
{
    using namespace nvcuda;

    __shared__ __align__(32) char smembuf[A_BYTES + W_BYTES];
    __shared__ float bsh[64];

    __half* Ah  = reinterpret_cast<__half*>(smembuf);             // 64 x A_LD
    __half* Wsh = reinterpret_cast<__half*>(smembuf + A_BYTES);   // 128 x W_LD
    float*  Csh = reinterpret_cast<float*>(smembuf);              // 64 x 64 (aliases Ah)

    int t = threadIdx.x;
    int row0 = blockIdx.x * ROWS_PB;
    if (t < 64) bsh[t] = bias[t];

    // Stage W': 8192 halves = 1024 uint4; 1 per thread.
    {
        const uint4* src = reinterpret_cast<const uint4*>(Wh);
        int k = t >> 3, q = t & 7;
        *reinterpret_cast<uint4*>(Wsh + k * W_LD + q * 8) = src[t];
    }

    // ---- SpMM phase: warp w -> rows row0+2w (lanes 0-15), row0+2w+1 (16-31)
    int warp = t >> 5, lane = t & 31;
    int m = warp * 2 + (lane >> 4);
    int l = lane & 15;
    int r = row0 + m;

    float4 acc = make_float4(0.f, 0.f, 0.f, 0.f);
    float2 g0 = make_float2(0.f, 0.f), g1 = make_float2(0.f, 0.f);

    if (r < NTOT) {
        int deg = g_deg[r];
        if (deg > ELL_CAP) deg = ELL_CAP;
        const float2*  ep = g_edges + (size_t)r * ELL_CAP;
        const __half2* eg = ego_in + l * 2;   // lane offset; row stride 32 half2

        int j = 0;
        for (; j + 8 <= deg; j += 8) {
            float4 e01 = *(const float4*)(ep + j);
            float4 e23 = *(const float4*)(ep + j + 2);
            float4 e45 = *(const float4*)(ep + j + 4);
            float4 e67 = *(const float4*)(ep + j + 6);
            uint2 x0 = *(const uint2*)(eg + (size_t)__float_as_int(e01.y) * 32);
            uint2 x1 = *(const uint2*)(eg + (size_t)__float_as_int(e01.w) * 32);
            uint2 x2 = *(const uint2*)(eg + (size_t)__float_as_int(e23.y) * 32);
            uint2 x3 = *(const uint2*)(eg + (size_t)__float_as_int(e23.w) * 32);
            uint2 x4 = *(const uint2*)(eg + (size_t)__float_as_int(e45.y) * 32);
            uint2 x5 = *(const uint2*)(eg + (size_t)__float_as_int(e45.w) * 32);
            uint2 x6 = *(const uint2*)(eg + (size_t)__float_as_int(e67.y) * 32);
            uint2 x7 = *(const uint2*)(eg + (size_t)__float_as_int(e67.w) * 32);

            // fp16 chunk accumulation (2 HFMA2 per edge), fp32 flush per chunk
            __half2 a0 = bits_h2(0u), a1 = bits_h2(0u);
            __half2 w;
            w = bits_h2(__float_as_uint(e01.x));
            a0 = __hfma2(w, bits_h2(x0.x), a0); a1 = __hfma2(w, bits_h2(x0.y), a1);
            w = bits_h2(__float_as_uint(e01.z));
            a0 = __hfma2(w, bits_h2(x1.x), a0); a1 = __hfma2(w, bits_h2(x1.y), a1);
            w = bits_h2(__float_as_uint(e23.x));
            a0 = __hfma2(w, bits_h2(x2.x), a0); a1 = __hfma2(w, bits_h2(x2.y), a1);
            w = bits_h2(__float_as_uint(e23.z));
            a0 = __hfma2(w, bits_h2(x3.x), a0); a1 = __hfma2(w, bits_h2(x3.y), a1);
            w = bits_h2(__float_as_uint(e45.x));
            a0 = __hfma2(w, bits_h2(x4.x), a0); a1 = __hfma2(w, bits_h2(x4.y), a1);
            w = bits_h2(__float_as_uint(e45.z));
            a0 = __hfma2(w, bits_h2(x5.x), a0); a1 = __hfma2(w, bits_h2(x5.y), a1);
            w = bits_h2(__float_as_uint(e67.x));
            a0 = __hfma2(w, bits_h2(x6.x), a0); a1 = __hfma2(w, bits_h2(x6.y), a1);
            w = bits_h2(__float_as_uint(e67.z));
            a0 = __hfma2(w, bits_h2(x7.x), a0); a1 = __hfma2(w, bits_h2(x7.y), a1);

            float2 f0 = __half22float2(a0);
            float2 f1 = __half22float2(a1);
            acc.x += f0.x; acc.y += f0.y; acc.z += f1.x; acc.w += f1.y;
        }
        for (; j + 2 <= deg; j += 2) {      // fp32 tail
            float4 e01 = *(const float4*)(ep + j);
            uint2 x0 = *(const uint2*)(eg + (size_t)__float_as_int(e01.y) * 32);
            uint2 x1 = *(const uint2*)(eg + (size_t)__float_as_int(e01.w) * 32);
            accum_f(acc, __low2float(bits_h2(__float_as_uint(e01.x))), x0);
            accum_f(acc, __low2float(bits_h2(__float_as_uint(e01.z))), x1);
        }
        for (; j < deg; ++j) {
            float2 e = ep[j];
            uint2 x = *(const uint2*)(eg + (size_t)__float_as_int(e.y) * 32);
            accum_f(acc, __low2float(bits_h2(__float_as_uint(e.x))), x);
        }

        uint2 eh = *reinterpret_cast<const uint2*>(ego_in + (size_t)r * 32 + l * 2);
        g0 = __half22float2(bits_h2(eh.x));
        g1 = __half22float2(bits_h2(eh.y));
    }

    // A' row -> shared (fp16): [side | side*ego]
    {
        uint2 s, p;
        s.x = h2_bits(__floats2half2_rn(acc.x, acc.y));
        s.y = h2_bits(__floats2half2_rn(acc.z, acc.w));
        p.x = h2_bits(__floats2half2_rn(acc.x * g0.x, acc.y * g0.y));
        p.y = h2_bits(__floats2half2_rn(acc.z * g1.x, acc.w * g1.y));
        *reinterpret_cast<uint2*>(Ah + m * A_LD + l * 4)      = s;
        *reinterpret_cast<uint2*>(Ah + m * A_LD + 64 + l * 4) = p;
    }
    __syncthreads();

    // ---- MMA phase: C (64x64) = 4x4 tiles of 16x16; warps 0-15, one each
    wmma::fragment<wmma::accumulator, 16, 16, 16, float> cfrag;
    int tr = (warp >> 2) & 3, tc = warp & 3;
    if (warp < 16) {
        wmma::fill_fragment(cfrag, 0.f);
        #pragma unroll
        for (int kk = 0; kk < 8; ++kk) {
            wmma::fragment<wmma::matrix_a, 16, 16, 16, __half, wmma::row_major> a;
            wmma::fragment<wmma::matrix_b, 16, 16, 16, __half, wmma::row_major> b;
            wmma::load_matrix_sync(a, Ah + (tr * 16) * A_LD + kk * 16, A_LD);
            wmma::load_matrix_sync(b, Wsh + (kk * 16) * W_LD + tc * 16, W_LD);
            wmma::mma_sync(cfrag, a, b, cfrag);
        }
    }
    __syncthreads();   // all A reads done before Csh overwrites Ah
    if (warp < 16)
        wmma::store_matrix_sync(Csh + (tr * 16) * 64 + tc * 16, cfrag, 64,
                                wmma::mem_row_major);
    __syncthreads();

    // ---- Epilogue: 1024 threads; thread -> (row ty, 4-col chunk tx)
    int ty = t >> 4, tx = t & 15;
    int c0i = tx * 4;

    float v[4];
    #pragma unroll
    for (int jj = 0; jj < 4; ++jj) {
        float x = Csh[ty * 64 + c0i + jj] + bsh[c0i + jj];
        x = (x > 0.f) ? x : 0.2f * x;
        v[jj] = x;
    }
    float sq = v[0]*v[0] + v[1]*v[1] + v[2]*v[2] + v[3]*v[3];
    #pragma unroll
    for (int off = 8; off; off >>= 1)
        sq += __shfl_xor_sync(0xffffffffu, sq, off, 16);
    float inv = 1.0f / fmaxf(sqrtf(sq), 1e-12f);

    int rr = row0 + ty;
    if (rr < NTOT) {
        if (write_ego) {
            uint2 h;
            h.x = h2_bits(__floats2half2_rn(v[0], v[1]));
            h.y = h2_bits(__floats2half2_rn(v[2], v[3]));
            *reinterpret_cast<uint2*>(ego_out + (size_t)rr * 32 + c0i / 2) = h;
        }
        float4 n = make_float4(v[0] * inv, v[1] * inv, v[2] * inv, v[3] * inv);
        *(float4*)(norm_out + (size_t)rr * 64 + c0i) = n;
    }
}

// ---------------------------------------------------------------------------
// 4) Final gather; slice 0 reconstructed from raw masked embeddings
// ---------------------------------------------------------------------------
__global__ void gather_kernel(const int* __restrict__ users,
                              const int* __restrict__ pos,
                              const int* __restrict__ neg,
                              const float4* __restrict__ ue,
                              const float4* __restrict__ ie,
                              const int* __restrict__ usz,
                              const int* __restrict__ isz,
                              float4* __restrict__ out)
{
    int i = blockIdx.x * blockDim.x + threadIdx.x;   // 3 * BATCH * 64 float4s
    if (i >= 3 * BATCH * 64) return;
    int which = i / (BATCH * 64);
    int rem   = i - which * (BATCH * 64);
    int b  = rem >> 6;
    int q  = rem & 63;
    int slice = q >> 4;
    int qq    = q & 15;

    int row;
    if      (which == 0) row = users[b];
    else if (which == 1) row = N_USERS + pos[b];
    else                 row = N_USERS + neg[b];

    if (slice == 0) {
        float4 v; int sz;
        if (row < N_USERS) { v = ue[(size_t)row * 16 + qq];              sz = usz[row]; }
        else               { v = ie[(size_t)(row - N_USERS) * 16 + qq];  sz = isz[row - N_USERS]; }
        int c0 = qq * 4;
        if (c0 + 0 >= sz) v.x = 0.f;
        if (c0 + 1 >= sz) v.y = 0.f;
        if (c0 + 2 >= sz) v.z = 0.f;
        if (c0 + 3 >= sz) v.w = 0.f;
        out[i] = v;
    } else {
        const float4* src = (const float4*)&g_outs[slice][0];
        out[i] = src[(size_t)row * 16 + qq];
    }
}

// ---------------------------------------------------------------------------
// Launcher (graph-capturable)
// ---------------------------------------------------------------------------
extern "C" void kernel_launch(void* const* d_in, const int* in_sizes, int n_in,
                              void* d_out, int out_size)
{
    const float* user_emb   = (const float*)d_in[0];
    const float* item_emb   = (const float*)d_in[1];
    const float* W_gc       = (const float*)d_in[2];
    const float* b_gc       = (const float*)d_in[3];
    const float* W_bi       = (const float*)d_in[4];
    const float* b_bi       = (const float*)d_in[5];
    const float* adj_vals   = (const float*)d_in[6];
    const int*   adj_rows   = (const int*)d_in[7];
    const int*   adj_cols   = (const int*)d_in[8];
    const int*   user_sizes = (const int*)d_in[9];
    const int*   item_sizes = (const int*)d_in[10];
    const int*   users      = (const int*)d_in[11];
    const int*   pos_items  = (const int*)d_in[12];
    const int*   neg_items  = (const int*)d_in[13];

    float *outs;
    int   *deg;
    __half *wh;
    float *bs;
    __half2 *egoh;
    cudaGetSymbolAddress((void**)&outs, g_outs);
    cudaGetSymbolAddress((void**)&deg,  g_deg);
    cudaGetSymbolAddress((void**)&wh,   g_wh);
    cudaGetSymbolAddress((void**)&bs,   g_bs);
    cudaGetSymbolAddress((void**)&egoh, g_egoh);

    const size_t SLICE  = (size_t)NTOT * EMB;
    const size_t HSLICE = (size_t)NTOT * (EMB / 2);

    prep_w_kernel<<<(NLAYERS * 128 * 64 + 255) / 256, 256>>>(W_gc, W_bi, b_gc, b_bi);

    init_kernel<<<(NTOT * 16 + 255) / 256, 256>>>(
        (const float4*)user_emb, (const float4*)item_emb,
        user_sizes, item_sizes);

    cudaMemsetAsync(deg, 0, NTOT * sizeof(int), 0);
    scatter_kernel<<<(NNZ_C / 4 + 255) / 256, 256>>>(
        (const float4*)adj_vals, (const int4*)adj_rows, (const int4*)adj_cols);

    int cur = 0;
    for (int k = 0; k < NLAYERS; ++k) {
        layer_kernel<<<(NTOT + ROWS_PB - 1) / ROWS_PB, LTHREADS>>>(
            wh + (size_t)k * 128 * 64, bs + (size_t)k * 64,
            egoh + (size_t)cur * HSLICE, egoh + (size_t)(1 - cur) * HSLICE,
            outs + (size_t)(k + 1) * SLICE,
            (k + 1 < NLAYERS) ? 1 : 0);
        cur ^= 1;
    }

    gather_kernel<<<(3 * BATCH * 64 + 255) / 256, 256>>>(
        users, pos_items, neg_items,
        (const float4*)user_emb, (const float4*)item_emb,
        user_sizes, item_sizes, (float4*)d_out);
}

// round 14
// speedup vs baseline: 1.3325x; 1.3325x over previous
#include <cuda_runtime.h>
#include <cuda_fp16.h>
#include <mma.h>
#include <cstdint>
#include <cstddef>

#define N_USERS 60000
#define N_ITEMS 40000
#define NTOT    100000
#define EMB     64
#define NNZ_C   2560000
#define BATCH   4096
#define NLAYERS 3
#define ELL_CAP 64         // deg ~ Poisson(25.6); P(deg>64) ~ 1e-14 per row

#define ROWS_PB 32         // rows per block (round-12 proven geometry)
#define LTHREADS 512       // 32 rows x 16 lanes

// Scratch (__device__ globals; no allocation allowed)
__device__ __half2 g_egoh[2][(size_t)NTOT * (EMB / 2)]; // ping-pong fp16 ego
__device__ float   g_outs[4][(size_t)NTOT * EMB];       // slice 0 unused
__device__ float2  g_edges[(size_t)NTOT * ELL_CAP];     // (w as half2-bits, col), ELL
__device__ int     g_deg  [NTOT];
__device__ __half  g_wh [NLAYERS * 128 * 64];           // W' = [Wgc;Wbi] fp16 per layer
__device__ float   g_bs [NLAYERS * 64];                 // bgc + bbi per layer

__device__ __forceinline__ unsigned int h2_bits(__half2 v) {
    return *reinterpret_cast<unsigned int*>(&v);
}
__device__ __forceinline__ __half2 bits_h2(unsigned int b) {
    return *reinterpret_cast<__half2*>(&b);
}

// ---------------------------------------------------------------------------
// 0) One-time weight conversion: W' fp16 + summed bias
// ---------------------------------------------------------------------------
__global__ void prep_w_kernel(const float* __restrict__ Wgc,
                              const float* __restrict__ Wbi,
                              const float* __restrict__ bgc,
                              const float* __restrict__ bbi)
{
    int i = blockIdx.x * blockDim.x + threadIdx.x;
    if (i < NLAYERS * 128 * 64) {
        int k = i / 8192, rem = i - k * 8192;
        int kk = rem >> 6, n = rem & 63;
        float w = (kk < 64) ? Wgc[k * 4096 + kk * 64 + n]
                            : Wbi[k * 4096 + (kk - 64) * 64 + n];
        g_wh[i] = __float2half_rn(w);
    }
    if (i < NLAYERS * 64)
        g_bs[i] = bgc[i] + bbi[i];
}

// ---------------------------------------------------------------------------
// 1) masked ego -> fp16 egoh[0] only (slice 0 reconstructed in gather)
// ---------------------------------------------------------------------------
__global__ void init_kernel(const float4* __restrict__ ue,
                            const float4* __restrict__ ie,
                            const int* __restrict__ usz,
                            const int* __restrict__ isz)
{
    int i = blockIdx.x * blockDim.x + threadIdx.x;   // NTOT * 16 float4s
    if (i >= NTOT * 16) return;
    int r = i >> 4;
    int q = i & 15;
    int c0 = q * 4;
    float4 v; int sz;
    if (r < N_USERS) { v = ue[i];                              sz = usz[r]; }
    else             { v = ie[(size_t)(r - N_USERS) * 16 + q]; sz = isz[r - N_USERS]; }
    if (c0 + 0 >= sz) v.x = 0.f;
    if (c0 + 1 >= sz) v.y = 0.f;
    if (c0 + 2 >= sz) v.z = 0.f;
    if (c0 + 3 >= sz) v.w = 0.f;
    uint2 h;
    h.x = h2_bits(__floats2half2_rn(v.x, v.y));
    h.y = h2_bits(__floats2half2_rn(v.z, v.w));
    *reinterpret_cast<uint2*>(&g_egoh[0][(size_t)i * 2]) = h;
}

// ---------------------------------------------------------------------------
// 2) ELL scatter; edge record = (w as broadcast half2 bits, col bits)
// ---------------------------------------------------------------------------
__global__ void scatter_kernel(const float4* __restrict__ vals4,
                               const int4*   __restrict__ rows4,
                               const int4*   __restrict__ cols4)
{
    int i = blockIdx.x * blockDim.x + threadIdx.x;   // NNZ/4 threads
    if (i >= NNZ_C / 4) return;
    float4 v = vals4[i];
    int4   r = rows4[i];
    int4   c = cols4[i];

    #define PUT(vv, rr, cc) do {                                              \
        int p = atomicAdd(&g_deg[rr], 1);                                     \
        if (p < ELL_CAP) {                                                    \
            unsigned int wb = h2_bits(__float2half2_rn(vv));                  \
            g_edges[(size_t)(rr) * ELL_CAP + p] =                             \
                make_float2(__uint_as_float(wb), __int_as_float(cc));         \
        }                                                                     \
    } while (0)
    PUT(v.x, r.x, c.x);
    PUT(v.y, r.y, c.y);
    PUT(v.z, r.z, c.z);
    PUT(v.w, r.w, c.w);
    #undef PUT
}

// ---------------------------------------------------------------------------
// 3) Fused layer kernel: ELL SpMM (fp16 gather, HFMA2 chunk accum, fp32 flush)
//    -> A' in shared -> WMMA (32x64 out, K=128) -> bias/leakyReLU/norm.
//    Block: 512 threads = 32 rows x 16 lanes = 16 warps (warps 0-7 do MMA).
// ---------------------------------------------------------------------------
__device__ __forceinline__ void accum_f(float4& acc, float wv, uint2 u)
{
    float2 f0 = __half22float2(bits_h2(u.x));
    float2 f1 = __half22float2(bits_h2(u.y));
    acc.x += wv * f0.x;
    acc.y += wv * f0.y;
    acc.z += wv * f1.x;
    acc.w += wv * f1.y;
}

#define A_LD   136   // 128 + 8 halves
#define W_LD   72    // 64 + 8 halves
#define A_BYTES (ROWS_PB * A_LD * 2)   // 8704
#define W_BYTES (128 * W_LD * 2)       // 18432

__global__ void __launch_bounds__(LTHREADS) layer_kernel(
    const __half*  __restrict__ Wh,     const float* __restrict__ bias,
    const __half2* __restrict__ ego_in, __half2* __restrict__ ego_out,
    float* __restrict__ norm_out,       int write_ego)
{
    using namespace nvcuda;

    __shared__ __align__(32) char smembuf[A_BYTES + W_BYTES];
    __shared__ float bsh[64];

    __half* Ah  = reinterpret_cast<__half*>(smembuf);             // 32 x A_LD
    __half* Wsh = reinterpret_cast<__half*>(smembuf + A_BYTES);   // 128 x W_LD
    float*  Csh = reinterpret_cast<float*>(smembuf);              // 32 x 64 (aliases Ah)

    int t = threadIdx.x;
    int row0 = blockIdx.x * ROWS_PB;
    if (t < 64) bsh[t] = bias[t];

    // Stage W': 8192 halves = 1024 uint4; 2 per thread.
    {
        const uint4* src = reinterpret_cast<const uint4*>(Wh);
        #pragma unroll
        for (int jj = 0; jj < 2; ++jj) {
            int idx = t + jj * LTHREADS;
            int k = idx >> 3, q = idx & 7;
            *reinterpret_cast<uint4*>(Wsh + k * W_LD + q * 8) = src[idx];
        }
    }

    // ---- SpMM phase: warp w -> rows row0+2w (lanes 0-15), row0+2w+1 (16-31)
    int warp = t >> 5, lane = t & 31;
    int m = warp * 2 + (lane >> 4);
    int l = lane & 15;
    int r = row0 + m;

    float4 acc = make_float4(0.f, 0.f, 0.f, 0.f);
    float2 g0 = make_float2(0.f, 0.f), g1 = make_float2(0.f, 0.f);

    if (r < NTOT) {
        int deg = g_deg[r];
        if (deg > ELL_CAP) deg = ELL_CAP;
        const float2*  ep = g_edges + (size_t)r * ELL_CAP;
        const __half2* eg = ego_in + l * 2;   // lane offset; row stride 32 half2

        int j = 0;
        for (; j + 8 <= deg; j += 8) {
            float4 e01 = *(const float4*)(ep + j);
            float4 e23 = *(const float4*)(ep + j + 2);
            float4 e45 = *(const float4*)(ep + j + 4);
            float4 e67 = *(const float4*)(ep + j + 6);
            uint2 x0 = *(const uint2*)(eg + (size_t)__float_as_int(e01.y) * 32);
            uint2 x1 = *(const uint2*)(eg + (size_t)__float_as_int(e01.w) * 32);
            uint2 x2 = *(const uint2*)(eg + (size_t)__float_as_int(e23.y) * 32);
            uint2 x3 = *(const uint2*)(eg + (size_t)__float_as_int(e23.w) * 32);
            uint2 x4 = *(const uint2*)(eg + (size_t)__float_as_int(e45.y) * 32);
            uint2 x5 = *(const uint2*)(eg + (size_t)__float_as_int(e45.w) * 32);
            uint2 x6 = *(const uint2*)(eg + (size_t)__float_as_int(e67.y) * 32);
            uint2 x7 = *(const uint2*)(eg + (size_t)__float_as_int(e67.w) * 32);

            // fp16 chunk accumulation (2 HFMA2 per edge), fp32 flush per chunk
            __half2 a0 = bits_h2(0u), a1 = bits_h2(0u);
            __half2 w;
            w = bits_h2(__float_as_uint(e01.x));
            a0 = __hfma2(w, bits_h2(x0.x), a0); a1 = __hfma2(w, bits_h2(x0.y), a1);
            w = bits_h2(__float_as_uint(e01.z));
            a0 = __hfma2(w, bits_h2(x1.x), a0); a1 = __hfma2(w, bits_h2(x1.y), a1);
            w = bits_h2(__float_as_uint(e23.x));
            a0 = __hfma2(w, bits_h2(x2.x), a0); a1 = __hfma2(w, bits_h2(x2.y), a1);
            w = bits_h2(__float_as_uint(e23.z));
            a0 = __hfma2(w, bits_h2(x3.x), a0); a1 = __hfma2(w, bits_h2(x3.y), a1);
            w = bits_h2(__float_as_uint(e45.x));
            a0 = __hfma2(w, bits_h2(x4.x), a0); a1 = __hfma2(w, bits_h2(x4.y), a1);
            w = bits_h2(__float_as_uint(e45.z));
            a0 = __hfma2(w, bits_h2(x5.x), a0); a1 = __hfma2(w, bits_h2(x5.y), a1);
            w = bits_h2(__float_as_uint(e67.x));
            a0 = __hfma2(w, bits_h2(x6.x), a0); a1 = __hfma2(w, bits_h2(x6.y), a1);
            w = bits_h2(__float_as_uint(e67.z));
            a0 = __hfma2(w, bits_h2(x7.x), a0); a1 = __hfma2(w, bits_h2(x7.y), a1);

            float2 f0 = __half22float2(a0);
            float2 f1 = __half22float2(a1);
            acc.x += f0.x; acc.y += f0.y; acc.z += f1.x; acc.w += f1.y;
        }
        for (; j + 2 <= deg; j += 2) {      // fp32 tail
            float4 e01 = *(const float4*)(ep + j);
            uint2 x0 = *(const uint2*)(eg + (size_t)__float_as_int(e01.y) * 32);
            uint2 x1 = *(const uint2*)(eg + (size_t)__float_as_int(e01.w) * 32);
            accum_f(acc, __low2float(bits_h2(__float_as_uint(e01.x))), x0);
            accum_f(acc, __low2float(bits_h2(__float_as_uint(e01.z))), x1);
        }
        for (; j < deg; ++j) {
            float2 e = ep[j];
            uint2 x = *(const uint2*)(eg + (size_t)__float_as_int(e.y) * 32);
            accum_f(acc, __low2float(bits_h2(__float_as_uint(e.x))), x);
        }

        uint2 eh = *reinterpret_cast<const uint2*>(ego_in + (size_t)r * 32 + l * 2);
        g0 = __half22float2(bits_h2(eh.x));
        g1 = __half22float2(bits_h2(eh.y));
    }

    // A' row -> shared (fp16): [side | side*ego]
    {
        uint2 s, p;
        s.x = h2_bits(__floats2half2_rn(acc.x, acc.y));
        s.y = h2_bits(__floats2half2_rn(acc.z, acc.w));
        p.x = h2_bits(__floats2half2_rn(acc.x * g0.x, acc.y * g0.y));
        p.y = h2_bits(__floats2half2_rn(acc.z * g1.x, acc.w * g1.y));
        *reinterpret_cast<uint2*>(Ah + m * A_LD + l * 4)      = s;
        *reinterpret_cast<uint2*>(Ah + m * A_LD + 64 + l * 4) = p;
    }
    __syncthreads();

    // ---- MMA phase: C (32x64) = 2x4 tiles of 16x16; warps 0-7, one tile each
    wmma::fragment<wmma::accumulator, 16, 16, 16, float> cfrag;
    int tr = (warp >> 2) & 1, tc = warp & 3;
    if (warp < 8) {
        wmma::fill_fragment(cfrag, 0.f);
        #pragma unroll
        for (int kk = 0; kk < 8; ++kk) {
            wmma::fragment<wmma::matrix_a, 16, 16, 16, __half, wmma::row_major> a;
            wmma::fragment<wmma::matrix_b, 16, 16, 16, __half, wmma::row_major> b;
            wmma::load_matrix_sync(a, Ah + (tr * 16) * A_LD + kk * 16, A_LD);
            wmma::load_matrix_sync(b, Wsh + (kk * 16) * W_LD + tc * 16, W_LD);
            wmma::mma_sync(cfrag, a, b, cfrag);
        }
    }
    __syncthreads();   // all A reads done before Csh overwrites Ah
    if (warp < 8)
        wmma::store_matrix_sync(Csh + (tr * 16) * 64 + tc * 16, cfrag, 64,
                                wmma::mem_row_major);
    __syncthreads();

    // ---- Epilogue: 512 threads; thread -> (row ty, 4-col chunk tx)
    int ty = t >> 4, tx = t & 15;
    int c0i = tx * 4;

    float v[4];
    #pragma unroll
    for (int jj = 0; jj < 4; ++jj) {
        float x = Csh[ty * 64 + c0i + jj] + bsh[c0i + jj];
        x = (x > 0.f) ? x : 0.2f * x;
        v[jj] = x;
    }
    float sq = v[0]*v[0] + v[1]*v[1] + v[2]*v[2] + v[3]*v[3];
    #pragma unroll
    for (int off = 8; off; off >>= 1)
        sq += __shfl_xor_sync(0xffffffffu, sq, off, 16);
    float inv = 1.0f / fmaxf(sqrtf(sq), 1e-12f);

    int rr = row0 + ty;
    if (rr < NTOT) {
        if (write_ego) {
            uint2 h;
            h.x = h2_bits(__floats2half2_rn(v[0], v[1]));
            h.y = h2_bits(__floats2half2_rn(v[2], v[3]));
            *reinterpret_cast<uint2*>(ego_out + (size_t)rr * 32 + c0i / 2) = h;
        }
        float4 n = make_float4(v[0] * inv, v[1] * inv, v[2] * inv, v[3] * inv);
        *(float4*)(norm_out + (size_t)rr * 64 + c0i) = n;
    }
}

// ---------------------------------------------------------------------------
// 4) Final gather; slice 0 reconstructed from raw masked embeddings
// ---------------------------------------------------------------------------
__global__ void gather_kernel(const int* __restrict__ users,
                              const int* __restrict__ pos,
                              const int* __restrict__ neg,
                              const float4* __restrict__ ue,
                              const float4* __restrict__ ie,
                              const int* __restrict__ usz,
                              const int* __restrict__ isz,
                              float4* __restrict__ out)
{
    int i = blockIdx.x * blockDim.x + threadIdx.x;   // 3 * BATCH * 64 float4s
    if (i >= 3 * BATCH * 64) return;
    int which = i / (BATCH * 64);
    int rem   = i - which * (BATCH * 64);
    int b  = rem >> 6;
    int q  = rem & 63;
    int slice = q >> 4;
    int qq    = q & 15;

    int row;
    if      (which == 0) row = users[b];
    else if (which == 1) row = N_USERS + pos[b];
    else                 row = N_USERS + neg[b];

    if (slice == 0) {
        float4 v; int sz;
        if (row < N_USERS) { v = ue[(size_t)row * 16 + qq];              sz = usz[row]; }
        else               { v = ie[(size_t)(row - N_USERS) * 16 + qq];  sz = isz[row - N_USERS]; }
        int c0 = qq * 4;
        if (c0 + 0 >= sz) v.x = 0.f;
        if (c0 + 1 >= sz) v.y = 0.f;
        if (c0 + 2 >= sz) v.z = 0.f;
        if (c0 + 3 >= sz) v.w = 0.f;
        out[i] = v;
    } else {
        const float4* src = (const float4*)&g_outs[slice][0];
        out[i] = src[(size_t)row * 16 + qq];
    }
}

// ---------------------------------------------------------------------------
// Launcher (graph-capturable)
// ---------------------------------------------------------------------------
extern "C" void kernel_launch(void* const* d_in, const int* in_sizes, int n_in,
                              void* d_out, int out_size)
{
    const float* user_emb   = (const float*)d_in[0];
    const float* item_emb   = (const float*)d_in[1];
    const float* W_gc       = (const float*)d_in[2];
    const float* b_gc       = (const float*)d_in[3];
    const float* W_bi       = (const float*)d_in[4];
    const float* b_bi       = (const float*)d_in[5];
    const float* adj_vals   = (const float*)d_in[6];
    const int*   adj_rows   = (const int*)d_in[7];
    const int*   adj_cols   = (const int*)d_in[8];
    const int*   user_sizes = (const int*)d_in[9];
    const int*   item_sizes = (const int*)d_in[10];
    const int*   users      = (const int*)d_in[11];
    const int*   pos_items  = (const int*)d_in[12];
    const int*   neg_items  = (const int*)d_in[13];

    float *outs;
    int   *deg;
    __half *wh;
    float *bs;
    __half2 *egoh;
    cudaGetSymbolAddress((void**)&outs, g_outs);
    cudaGetSymbolAddress((void**)&deg,  g_deg);
    cudaGetSymbolAddress((void**)&wh,   g_wh);
    cudaGetSymbolAddress((void**)&bs,   g_bs);
    cudaGetSymbolAddress((void**)&egoh, g_egoh);

    const size_t SLICE  = (size_t)NTOT * EMB;
    const size_t HSLICE = (size_t)NTOT * (EMB / 2);

    prep_w_kernel<<<(NLAYERS * 128 * 64 + 255) / 256, 256>>>(W_gc, W_bi, b_gc, b_bi);

    init_kernel<<<(NTOT * 16 + 255) / 256, 256>>>(
        (const float4*)user_emb, (const float4*)item_emb,
        user_sizes, item_sizes);

    cudaMemsetAsync(deg, 0, NTOT * sizeof(int), 0);
    scatter_kernel<<<(NNZ_C / 4 + 255) / 256, 256>>>(
        (const float4*)adj_vals, (const int4*)adj_rows, (const int4*)adj_cols);

    int cur = 0;
    for (int k = 0; k < NLAYERS; ++k) {
        layer_kernel<<<(NTOT + ROWS_PB - 1) / ROWS_PB, LTHREADS>>>(
            wh + (size_t)k * 128 * 64, bs + (size_t)k * 64,
            egoh + (size_t)cur * HSLICE, egoh + (size_t)(1 - cur) * HSLICE,
            outs + (size_t)(k + 1) * SLICE,
            (k + 1 < NLAYERS) ? 1 : 0);
        cur ^= 1;
    }

    gather_kernel<<<(3 * BATCH * 64 + 255) / 256, 256>>>(
        users, pos_items, neg_items,
        (const float4*)user_emb, (const float4*)item_emb,
        user_sizes, item_sizes, (float4*)d_out);
}

// round 15
// speedup vs baseline: 1.4109x; 1.0588x over previous
#include <cuda_runtime.h>
#include <cuda_fp16.h>
#include <mma.h>
#include <cstdint>
#include <cstddef>

#define N_USERS 60000
#define N_ITEMS 40000
#define NTOT    100000
#define EMB     64
#define NNZ_C   2560000
#define BATCH   4096
#define NLAYERS 3
#define ELL_CAP 64         // deg ~ Poisson(25.6); P(deg>64) ~ 1e-14 per row

#define ROWS_PB 32         // rows per block
#define LTHREADS 512       // 32 rows x 16 lanes

// Scratch (__device__ globals; no allocation allowed)
__device__ __half2 g_egoh[2][(size_t)NTOT * (EMB / 2)]; // ping-pong fp16 ego
__device__ float   g_outs[4][(size_t)NTOT * EMB];       // slice 0 unused
__device__ float2  g_edges[(size_t)NTOT * ELL_CAP];     // (w as half2-bits, col), ELL
__device__ int     g_deg  [NTOT];
__device__ __half  g_wh [NLAYERS * 128 * 64];           // W' = [Wgc;Wbi] fp16 per layer
__device__ float   g_bs [NLAYERS * 64];                 // bgc + bbi per layer

__device__ __forceinline__ unsigned int h2_bits(__half2 v) {
    return *reinterpret_cast<unsigned int*>(&v);
}
__device__ __forceinline__ __half2 bits_h2(unsigned int b) {
    return *reinterpret_cast<__half2*>(&b);
}

// ---------------------------------------------------------------------------
// 0) One-time weight conversion: W' fp16 + summed bias
// ---------------------------------------------------------------------------
__global__ void prep_w_kernel(const float* __restrict__ Wgc,
                              const float* __restrict__ Wbi,
                              const float* __restrict__ bgc,
                              const float* __restrict__ bbi)
{
    int i = blockIdx.x * blockDim.x + threadIdx.x;
    if (i < NLAYERS * 128 * 64) {
        int k = i / 8192, rem = i - k * 8192;
        int kk = rem >> 6, n = rem & 63;
        float w = (kk < 64) ? Wgc[k * 4096 + kk * 64 + n]
                            : Wbi[k * 4096 + (kk - 64) * 64 + n];
        g_wh[i] = __float2half_rn(w);
    }
    if (i < NLAYERS * 64)
        g_bs[i] = bgc[i] + bbi[i];
}

// ---------------------------------------------------------------------------
// 1) masked ego -> fp16 egoh[0] only (slice 0 reconstructed in gather)
// ---------------------------------------------------------------------------
__global__ void init_kernel(const float4* __restrict__ ue,
                            const float4* __restrict__ ie,
                            const int* __restrict__ usz,
                            const int* __restrict__ isz)
{
    int i = blockIdx.x * blockDim.x + threadIdx.x;   // NTOT * 16 float4s
    if (i >= NTOT * 16) return;
    int r = i >> 4;
    int q = i & 15;
    int c0 = q * 4;
    float4 v; int sz;
    if (r < N_USERS) { v = ue[i];                              sz = usz[r]; }
    else             { v = ie[(size_t)(r - N_USERS) * 16 + q]; sz = isz[r - N_USERS]; }
    if (c0 + 0 >= sz) v.x = 0.f;
    if (c0 + 1 >= sz) v.y = 0.f;
    if (c0 + 2 >= sz) v.z = 0.f;
    if (c0 + 3 >= sz) v.w = 0.f;
    uint2 h;
    h.x = h2_bits(__floats2half2_rn(v.x, v.y));
    h.y = h2_bits(__floats2half2_rn(v.z, v.w));
    *reinterpret_cast<uint2*>(&g_egoh[0][(size_t)i * 2]) = h;
}

// ---------------------------------------------------------------------------
// 2) ELL scatter; edge record = (w as broadcast half2 bits, col bits)
// ---------------------------------------------------------------------------
__global__ void scatter_kernel(const float4* __restrict__ vals4,
                               const int4*   __restrict__ rows4,
                               const int4*   __restrict__ cols4)
{
    int i = blockIdx.x * blockDim.x + threadIdx.x;   // NNZ/4 threads
    if (i >= NNZ_C / 4) return;
    float4 v = vals4[i];
    int4   r = rows4[i];
    int4   c = cols4[i];

    #define PUT(vv, rr, cc) do {                                              \
        int p = atomicAdd(&g_deg[rr], 1);                                     \
        if (p < ELL_CAP) {                                                    \
            unsigned int wb = h2_bits(__float2half2_rn(vv));                  \
            g_edges[(size_t)(rr) * ELL_CAP + p] =                             \
                make_float2(__uint_as_float(wb), __int_as_float(cc));         \
        }                                                                     \
    } while (0)
    PUT(v.x, r.x, c.x);
    PUT(v.y, r.y, c.y);
    PUT(v.z, r.z, c.z);
    PUT(v.w, r.w, c.w);
    #undef PUT
}

// ---------------------------------------------------------------------------
// 3) Fused layer kernel: ELL SpMM (fp16 gather, HFMA2 chunk accum, fp32 flush)
//    -> A' in shared -> WMMA (32x64 out, K=128) -> bias/leakyReLU/norm.
//    Block: 512 threads = 32 rows x 16 lanes; launch_bounds(512,4) caps regs
//    at 32 so 4 blocks fit per SM (regfile was the occupancy limiter at 38).
// ---------------------------------------------------------------------------
__device__ __forceinline__ void accum_f(float4& acc, float wv, uint2 u)
{
    float2 f0 = __half22float2(bits_h2(u.x));
    float2 f1 = __half22float2(bits_h2(u.y));
    acc.x += wv * f0.x;
    acc.y += wv * f0.y;
    acc.z += wv * f1.x;
    acc.w += wv * f1.y;
}

#define A_LD   136   // 128 + 8 halves
#define W_LD   72    // 64 + 8 halves
#define A_BYTES (ROWS_PB * A_LD * 2)   // 8704
#define W_BYTES (128 * W_LD * 2)       // 18432

__global__ void __launch_bounds__(LTHREADS, 4) layer_kernel(
    const __half*  __restrict__ Wh,     const float* __restrict__ bias,
    const __half2* __restrict__ ego_in, __half2* __restrict__ ego_out,
    float* __restrict__ norm_out,       int write_ego)
{
    using namespace nvcuda;

    __shared__ __align__(32) char smembuf[A_BYTES + W_BYTES];
    __shared__ float bsh[64];

    __half* Ah  = reinterpret_cast<__half*>(smembuf);             // 32 x A_LD
    __half* Wsh = reinterpret_cast<__half*>(smembuf + A_BYTES);   // 128 x W_LD
    float*  Csh = reinterpret_cast<float*>(smembuf);              // 32 x 64 (aliases Ah)

    int t = threadIdx.x;
    int row0 = blockIdx.x * ROWS_PB;
    if (t < 64) bsh[t] = bias[t];

    // Stage W': 8192 halves = 1024 uint4; 2 per thread.
    {
        const uint4* src = reinterpret_cast<const uint4*>(Wh);
        #pragma unroll
        for (int jj = 0; jj < 2; ++jj) {
            int idx = t + jj * LTHREADS;
            int k = idx >> 3, q = idx & 7;
            *reinterpret_cast<uint4*>(Wsh + k * W_LD + q * 8) = src[idx];
        }
    }

    // ---- SpMM phase: warp w -> rows row0+2w (lanes 0-15), row0+2w+1 (16-31)
    int warp = t >> 5, lane = t & 31;
    int m = warp * 2 + (lane >> 4);
    int l = lane & 15;
    int r = row0 + m;

    float4 acc = make_float4(0.f, 0.f, 0.f, 0.f);
    float2 g0 = make_float2(0.f, 0.f), g1 = make_float2(0.f, 0.f);

    if (r < NTOT) {
        int deg = g_deg[r];
        if (deg > ELL_CAP) deg = ELL_CAP;
        const float2*  ep = g_edges + (size_t)r * ELL_CAP;
        const __half2* eg = ego_in + l * 2;   // lane offset; row stride 32 half2

        int j = 0;
        for (; j + 8 <= deg; j += 8) {
            float4 e01 = *(const float4*)(ep + j);
            float4 e23 = *(const float4*)(ep + j + 2);
            float4 e45 = *(const float4*)(ep + j + 4);
            float4 e67 = *(const float4*)(ep + j + 6);
            uint2 x0 = *(const uint2*)(eg + (size_t)__float_as_int(e01.y) * 32);
            uint2 x1 = *(const uint2*)(eg + (size_t)__float_as_int(e01.w) * 32);
            uint2 x2 = *(const uint2*)(eg + (size_t)__float_as_int(e23.y) * 32);
            uint2 x3 = *(const uint2*)(eg + (size_t)__float_as_int(e23.w) * 32);
            uint2 x4 = *(const uint2*)(eg + (size_t)__float_as_int(e45.y) * 32);
            uint2 x5 = *(const uint2*)(eg + (size_t)__float_as_int(e45.w) * 32);
            uint2 x6 = *(const uint2*)(eg + (size_t)__float_as_int(e67.y) * 32);
            uint2 x7 = *(const uint2*)(eg + (size_t)__float_as_int(e67.w) * 32);

            // fp16 chunk accumulation (2 HFMA2 per edge), fp32 flush per chunk
            __half2 a0 = bits_h2(0u), a1 = bits_h2(0u);
            __half2 w;
            w = bits_h2(__float_as_uint(e01.x));
            a0 = __hfma2(w, bits_h2(x0.x), a0); a1 = __hfma2(w, bits_h2(x0.y), a1);
            w = bits_h2(__float_as_uint(e01.z));
            a0 = __hfma2(w, bits_h2(x1.x), a0); a1 = __hfma2(w, bits_h2(x1.y), a1);
            w = bits_h2(__float_as_uint(e23.x));
            a0 = __hfma2(w, bits_h2(x2.x), a0); a1 = __hfma2(w, bits_h2(x2.y), a1);
            w = bits_h2(__float_as_uint(e23.z));
            a0 = __hfma2(w, bits_h2(x3.x), a0); a1 = __hfma2(w, bits_h2(x3.y), a1);
            w = bits_h2(__float_as_uint(e45.x));
            a0 = __hfma2(w, bits_h2(x4.x), a0); a1 = __hfma2(w, bits_h2(x4.y), a1);
            w = bits_h2(__float_as_uint(e45.z));
            a0 = __hfma2(w, bits_h2(x5.x), a0); a1 = __hfma2(w, bits_h2(x5.y), a1);
            w = bits_h2(__float_as_uint(e67.x));
            a0 = __hfma2(w, bits_h2(x6.x), a0); a1 = __hfma2(w, bits_h2(x6.y), a1);
            w = bits_h2(__float_as_uint(e67.z));
            a0 = __hfma2(w, bits_h2(x7.x), a0); a1 = __hfma2(w, bits_h2(x7.y), a1);

            float2 f0 = __half22float2(a0);
            float2 f1 = __half22float2(a1);
            acc.x += f0.x; acc.y += f0.y; acc.z += f1.x; acc.w += f1.y;
        }
        for (; j + 2 <= deg; j += 2) {      // fp32 tail
            float4 e01 = *(const float4*)(ep + j);
            uint2 x0 = *(const uint2*)(eg + (size_t)__float_as_int(e01.y) * 32);
            uint2 x1 = *(const uint2*)(eg + (size_t)__float_as_int(e01.w) * 32);
            accum_f(acc, __low2float(bits_h2(__float_as_uint(e01.x))), x0);
            accum_f(acc, __low2float(bits_h2(__float_as_uint(e01.z))), x1);
        }
        for (; j < deg; ++j) {
            float2 e = ep[j];
            uint2 x = *(const uint2*)(eg + (size_t)__float_as_int(e.y) * 32);
            accum_f(acc, __low2float(bits_h2(__float_as_uint(e.x))), x);
        }

        uint2 eh = *reinterpret_cast<const uint2*>(ego_in + (size_t)r * 32 + l * 2);
        g0 = __half22float2(bits_h2(eh.x));
        g1 = __half22float2(bits_h2(eh.y));
    }

    // A' row -> shared (fp16): [side | side*ego]
    {
        uint2 s, p;
        s.x = h2_bits(__floats2half2_rn(acc.x, acc.y));
        s.y = h2_bits(__floats2half2_rn(acc.z, acc.w));
        p.x = h2_bits(__floats2half2_rn(acc.x * g0.x, acc.y * g0.y));
        p.y = h2_bits(__floats2half2_rn(acc.z * g1.x, acc.w * g1.y));
        *reinterpret_cast<uint2*>(Ah + m * A_LD + l * 4)      = s;
        *reinterpret_cast<uint2*>(Ah + m * A_LD + 64 + l * 4) = p;
    }
    __syncthreads();

    // ---- MMA phase: C (32x64) = 2x4 tiles of 16x16; warps 0-7, one tile each
    wmma::fragment<wmma::accumulator, 16, 16, 16, float> cfrag;
    int tr = (warp >> 2) & 1, tc = warp & 3;
    if (warp < 8) {
        wmma::fill_fragment(cfrag, 0.f);
        #pragma unroll
        for (int kk = 0; kk < 8; ++kk) {
            wmma::fragment<wmma::matrix_a, 16, 16, 16, __half, wmma::row_major> a;
            wmma::fragment<wmma::matrix_b, 16, 16, 16, __half, wmma::row_major> b;
            wmma::load_matrix_sync(a, Ah + (tr * 16) * A_LD + kk * 16, A_LD);
            wmma::load_matrix_sync(b, Wsh + (kk * 16) * W_LD + tc * 16, W_LD);
            wmma::mma_sync(cfrag, a, b, cfrag);
        }
    }
    __syncthreads();   // all A reads done before Csh overwrites Ah
    if (warp < 8)
        wmma::store_matrix_sync(Csh + (tr * 16) * 64 + tc * 16, cfrag, 64,
                                wmma::mem_row_major);
    __syncthreads();

    // ---- Epilogue: 512 threads; thread -> (row ty, 4-col chunk tx)
    int ty = t >> 4, tx = t & 15;
    int c0i = tx * 4;

    float v[4];
    #pragma unroll
    for (int jj = 0; jj < 4; ++jj) {
        float x = Csh[ty * 64 + c0i + jj] + bsh[c0i + jj];
        x = (x > 0.f) ? x : 0.2f * x;
        v[jj] = x;
    }
    float sq = v[0]*v[0] + v[1]*v[1] + v[2]*v[2] + v[3]*v[3];
    #pragma unroll
    for (int off = 8; off; off >>= 1)
        sq += __shfl_xor_sync(0xffffffffu, sq, off, 16);
    float inv = 1.0f / fmaxf(sqrtf(sq), 1e-12f);

    int rr = row0 + ty;
    if (rr < NTOT) {
        if (write_ego) {
            uint2 h;
            h.x = h2_bits(__floats2half2_rn(v[0], v[1]));
            h.y = h2_bits(__floats2half2_rn(v[2], v[3]));
            *reinterpret_cast<uint2*>(ego_out + (size_t)rr * 32 + c0i / 2) = h;
        }
        float4 n = make_float4(v[0] * inv, v[1] * inv, v[2] * inv, v[3] * inv);
        *(float4*)(norm_out + (size_t)rr * 64 + c0i) = n;
    }
}

// ---------------------------------------------------------------------------
// 4) Final gather; slice 0 reconstructed from raw masked embeddings
// ---------------------------------------------------------------------------
__global__ void gather_kernel(const int* __restrict__ users,
                              const int* __restrict__ pos,
                              const int* __restrict__ neg,
                              const float4* __restrict__ ue,
                              const float4* __restrict__ ie,
                              const int* __restrict__ usz,
                              const int* __restrict__ isz,
                              float4* __restrict__ out)
{
    int i = blockIdx.x * blockDim.x + threadIdx.x;   // 3 * BATCH * 64 float4s
    if (i >= 3 * BATCH * 64) return;
    int which = i / (BATCH * 64);
    int rem   = i - which * (BATCH * 64);
    int b  = rem >> 6;
    int q  = rem & 63;
    int slice = q >> 4;
    int qq    = q & 15;

    int row;
    if      (which == 0) row = users[b];
    else if (which == 1) row = N_USERS + pos[b];
    else                 row = N_USERS + neg[b];

    if (slice == 0) {
        float4 v; int sz;
        if (row < N_USERS) { v = ue[(size_t)row * 16 + qq];              sz = usz[row]; }
        else               { v = ie[(size_t)(row - N_USERS) * 16 + qq];  sz = isz[row - N_USERS]; }
        int c0 = qq * 4;
        if (c0 + 0 >= sz) v.x = 0.f;
        if (c0 + 1 >= sz) v.y = 0.f;
        if (c0 + 2 >= sz) v.z = 0.f;
        if (c0 + 3 >= sz) v.w = 0.f;
        out[i] = v;
    } else {
        const float4* src = (const float4*)&g_outs[slice][0];
        out[i] = src[(size_t)row * 16 + qq];
    }
}

// ---------------------------------------------------------------------------
// Launcher (graph-capturable)
// ---------------------------------------------------------------------------
extern "C" void kernel_launch(void* const* d_in, const int* in_sizes, int n_in,
                              void* d_out, int out_size)
{
    const float* user_emb   = (const float*)d_in[0];
    const float* item_emb   = (const float*)d_in[1];
    const float* W_gc       = (const float*)d_in[2];
    const float* b_gc       = (const float*)d_in[3];
    const float* W_bi       = (const float*)d_in[4];
    const float* b_bi       = (const float*)d_in[5];
    const float* adj_vals   = (const float*)d_in[6];
    const int*   adj_rows   = (const int*)d_in[7];
    const int*   adj_cols   = (const int*)d_in[8];
    const int*   user_sizes = (const int*)d_in[9];
    const int*   item_sizes = (const int*)d_in[10];
    const int*   users      = (const int*)d_in[11];
    const int*   pos_items  = (const int*)d_in[12];
    const int*   neg_items  = (const int*)d_in[13];

    float *outs;
    int   *deg;
    __half *wh;
    float *bs;
    __half2 *egoh;
    cudaGetSymbolAddress((void**)&outs, g_outs);
    cudaGetSymbolAddress((void**)&deg,  g_deg);
    cudaGetSymbolAddress((void**)&wh,   g_wh);
    cudaGetSymbolAddress((void**)&bs,   g_bs);
    cudaGetSymbolAddress((void**)&egoh, g_egoh);

    const size_t SLICE  = (size_t)NTOT * EMB;
    const size_t HSLICE = (size_t)NTOT * (EMB / 2);

    prep_w_kernel<<<(NLAYERS * 128 * 64 + 255) / 256, 256>>>(W_gc, W_bi, b_gc, b_bi);

    init_kernel<<<(NTOT * 16 + 255) / 256, 256>>>(
        (const float4*)user_emb, (const float4*)item_emb,
        user_sizes, item_sizes);

    cudaMemsetAsync(deg, 0, NTOT * sizeof(int), 0);
    scatter_kernel<<<(NNZ_C / 4 + 255) / 256, 256>>>(
        (const float4*)adj_vals, (const int4*)adj_rows, (const int4*)adj_cols);

    int cur = 0;
    for (int k = 0; k < NLAYERS; ++k) {
        layer_kernel<<<(NTOT + ROWS_PB - 1) / ROWS_PB, LTHREADS>>>(
            wh + (size_t)k * 128 * 64, bs + (size_t)k * 64,
            egoh + (size_t)cur * HSLICE, egoh + (size_t)(1 - cur) * HSLICE,
            outs + (size_t)(k + 1) * SLICE,
            (k + 1 < NLAYERS) ? 1 : 0);
        cur ^= 1;
    }

    gather_kernel<<<(3 * BATCH * 64 + 255) / 256, 256>>>(
        users, pos_items, neg_items,
        (const float4*)user_emb, (const float4*)item_emb,
        user_sizes, item_sizes, (float4*)d_out);
}

// round 16
// speedup vs baseline: 1.4590x; 1.0341x over previous
#include <cuda_runtime.h>
#include <cuda_fp16.h>
#include <mma.h>
#include <cstdint>
#include <cstddef>

#define N_USERS 60000
#define N_ITEMS 40000
#define NTOT    100000
#define EMB     64
#define NNZ_C   2560000
#define BATCH   4096
#define NLAYERS 3
#define ELL_CAP 64         // deg ~ Poisson(25.6); P(deg>64) ~ 1e-14 per row

#define ROWS_PB 32         // rows per block
#define LTHREADS 512       // 32 rows x 16 lanes

// preproc grid partition
#define SCAT_BLOCKS  ((NNZ_C / 4 + 255) / 256)          // 2500
#define INIT_BLOCKS  ((NTOT * 16 + 255) / 256)          // 6250
#define PREPW_BLOCKS ((NLAYERS * 128 * 64 + 255) / 256) // 96

// Scratch (__device__ globals; no allocation allowed)
__device__ __half2 g_egoh[2][(size_t)NTOT * (EMB / 2)]; // ping-pong fp16 ego
__device__ float   g_outs[4][(size_t)NTOT * EMB];       // slice 0 unused
__device__ float2  g_edges[(size_t)NTOT * ELL_CAP];     // (w half2-bits, byteoff), ELL
__device__ int     g_deg  [NTOT];
__device__ __half  g_wh [NLAYERS * 128 * 64];           // W' = [Wgc;Wbi] fp16 per layer
__device__ float   g_bs [NLAYERS * 64];                 // bgc + bbi per layer

__device__ __forceinline__ unsigned int h2_bits(__half2 v) {
    return *reinterpret_cast<unsigned int*>(&v);
}
__device__ __forceinline__ __half2 bits_h2(unsigned int b) {
    return *reinterpret_cast<__half2*>(&b);
}

// ---------------------------------------------------------------------------
// 1) Fused preprocessing: [scatter | init | prep_w] partitioned by blockIdx.
//    All three are data-independent; g_deg must be zeroed before launch.
//    Edge record stores (w as broadcast half2, col*128 = byte offset).
// ---------------------------------------------------------------------------
__global__ void preproc_kernel(const float4* __restrict__ vals4,
                               const int4*   __restrict__ rows4,
                               const int4*   __restrict__ cols4,
                               const float4* __restrict__ ue,
                               const float4* __restrict__ ie,
                               const int* __restrict__ usz,
                               const int* __restrict__ isz,
                               const float* __restrict__ Wgc,
                               const float* __restrict__ Wbi,
                               const float* __restrict__ bgc,
                               const float* __restrict__ bbi)
{
    int b = blockIdx.x;
    if (b < SCAT_BLOCKS) {
        // ---- ELL scatter
        int i = b * 256 + threadIdx.x;
        if (i >= NNZ_C / 4) return;
        float4 v = vals4[i];
        int4   r = rows4[i];
        int4   c = cols4[i];
        #define PUT(vv, rr, cc) do {                                           \
            int p = atomicAdd(&g_deg[rr], 1);                                  \
            if (p < ELL_CAP) {                                                 \
                unsigned int wb = h2_bits(__float2half2_rn(vv));               \
                g_edges[(size_t)(rr) * ELL_CAP + p] =                          \
                    make_float2(__uint_as_float(wb), __int_as_float((cc) << 7));\
            }                                                                  \
        } while (0)
        PUT(v.x, r.x, c.x);
        PUT(v.y, r.y, c.y);
        PUT(v.z, r.z, c.z);
        PUT(v.w, r.w, c.w);
        #undef PUT
    } else if (b < SCAT_BLOCKS + INIT_BLOCKS) {
        // ---- masked ego -> fp16 egoh[0]
        int i = (b - SCAT_BLOCKS) * 256 + threadIdx.x;
        if (i >= NTOT * 16) return;
        int r = i >> 4;
        int q = i & 15;
        int c0 = q * 4;
        float4 v; int sz;
        if (r < N_USERS) { v = ue[i];                              sz = usz[r]; }
        else             { v = ie[(size_t)(r - N_USERS) * 16 + q]; sz = isz[r - N_USERS]; }
        if (c0 + 0 >= sz) v.x = 0.f;
        if (c0 + 1 >= sz) v.y = 0.f;
        if (c0 + 2 >= sz) v.z = 0.f;
        if (c0 + 3 >= sz) v.w = 0.f;
        uint2 h;
        h.x = h2_bits(__floats2half2_rn(v.x, v.y));
        h.y = h2_bits(__floats2half2_rn(v.z, v.w));
        *reinterpret_cast<uint2*>(&g_egoh[0][(size_t)i * 2]) = h;
    } else {
        // ---- W' fp16 conversion + summed bias
        int i = (b - SCAT_BLOCKS - INIT_BLOCKS) * 256 + threadIdx.x;
        if (i < NLAYERS * 128 * 64) {
            int k = i / 8192, rem = i - k * 8192;
            int kk = rem >> 6, n = rem & 63;
            float w = (kk < 64) ? Wgc[k * 4096 + kk * 64 + n]
                                : Wbi[k * 4096 + (kk - 64) * 64 + n];
            g_wh[i] = __float2half_rn(w);
        }
        if (i < NLAYERS * 64)
            g_bs[i] = bgc[i] + bbi[i];
    }
}

// ---------------------------------------------------------------------------
// 2) Fused layer kernel: ELL SpMM (fp16 gather, HFMA2 chunk accum, fp32 flush)
//    -> A' in shared -> WMMA (32x64 out, K=128) -> bias/leakyReLU/norm.
//    Gather address = per-lane char base + pre-scaled byte offset (1 IMAD).
// ---------------------------------------------------------------------------
__device__ __forceinline__ void accum_f(float4& acc, float wv, uint2 u)
{
    float2 f0 = __half22float2(bits_h2(u.x));
    float2 f1 = __half22float2(bits_h2(u.y));
    acc.x += wv * f0.x;
    acc.y += wv * f0.y;
    acc.z += wv * f1.x;
    acc.w += wv * f1.y;
}

#define A_LD   136   // 128 + 8 halves
#define W_LD   72    // 64 + 8 halves
#define A_BYTES (ROWS_PB * A_LD * 2)   // 8704
#define W_BYTES (128 * W_LD * 2)       // 18432

__global__ void __launch_bounds__(LTHREADS, 4) layer_kernel(
    const __half*  __restrict__ Wh,     const float* __restrict__ bias,
    const __half2* __restrict__ ego_in, __half2* __restrict__ ego_out,
    float* __restrict__ norm_out,       int write_ego)
{
    using namespace nvcuda;

    __shared__ __align__(32) char smembuf[A_BYTES + W_BYTES];
    __shared__ float bsh[64];

    __half* Ah  = reinterpret_cast<__half*>(smembuf);             // 32 x A_LD
    __half* Wsh = reinterpret_cast<__half*>(smembuf + A_BYTES);   // 128 x W_LD
    float*  Csh = reinterpret_cast<float*>(smembuf);              // 32 x 64 (aliases Ah)

    int t = threadIdx.x;
    int row0 = blockIdx.x * ROWS_PB;
    if (t < 64) bsh[t] = bias[t];

    // Stage W': 8192 halves = 1024 uint4; 2 per thread.
    {
        const uint4* src = reinterpret_cast<const uint4*>(Wh);
        #pragma unroll
        for (int jj = 0; jj < 2; ++jj) {
            int idx = t + jj * LTHREADS;
            int k = idx >> 3, q = idx & 7;
            *reinterpret_cast<uint4*>(Wsh + k * W_LD + q * 8) = src[idx];
        }
    }

    // ---- SpMM phase: warp w -> rows row0+2w (lanes 0-15), row0+2w+1 (16-31)
    int warp = t >> 5, lane = t & 31;
    int m = warp * 2 + (lane >> 4);
    int l = lane & 15;
    int r = row0 + m;

    float4 acc = make_float4(0.f, 0.f, 0.f, 0.f);
    float2 g0 = make_float2(0.f, 0.f), g1 = make_float2(0.f, 0.f);

    if (r < NTOT) {
        int deg = g_deg[r];
        if (deg > ELL_CAP) deg = ELL_CAP;
        const float2* ep = g_edges + (size_t)r * ELL_CAP;
        const char*  egc = reinterpret_cast<const char*>(ego_in) + l * 8;

        #define GAT(e) (*reinterpret_cast<const uint2*>(egc + (unsigned)__float_as_int(e)))

        int j = 0;
        for (; j + 8 <= deg; j += 8) {
            float4 e01 = *(const float4*)(ep + j);
            float4 e23 = *(const float4*)(ep + j + 2);
            float4 e45 = *(const float4*)(ep + j + 4);
            float4 e67 = *(const float4*)(ep + j + 6);
            uint2 x0 = GAT(e01.y);
            uint2 x1 = GAT(e01.w);
            uint2 x2 = GAT(e23.y);
            uint2 x3 = GAT(e23.w);
            uint2 x4 = GAT(e45.y);
            uint2 x5 = GAT(e45.w);
            uint2 x6 = GAT(e67.y);
            uint2 x7 = GAT(e67.w);

            // fp16 chunk accumulation (2 HFMA2 per edge), fp32 flush per chunk
            __half2 a0 = bits_h2(0u), a1 = bits_h2(0u);
            __half2 w;
            w = bits_h2(__float_as_uint(e01.x));
            a0 = __hfma2(w, bits_h2(x0.x), a0); a1 = __hfma2(w, bits_h2(x0.y), a1);
            w = bits_h2(__float_as_uint(e01.z));
            a0 = __hfma2(w, bits_h2(x1.x), a0); a1 = __hfma2(w, bits_h2(x1.y), a1);
            w = bits_h2(__float_as_uint(e23.x));
            a0 = __hfma2(w, bits_h2(x2.x), a0); a1 = __hfma2(w, bits_h2(x2.y), a1);
            w = bits_h2(__float_as_uint(e23.z));
            a0 = __hfma2(w, bits_h2(x3.x), a0); a1 = __hfma2(w, bits_h2(x3.y), a1);
            w = bits_h2(__float_as_uint(e45.x));
            a0 = __hfma2(w, bits_h2(x4.x), a0); a1 = __hfma2(w, bits_h2(x4.y), a1);
            w = bits_h2(__float_as_uint(e45.z));
            a0 = __hfma2(w, bits_h2(x5.x), a0); a1 = __hfma2(w, bits_h2(x5.y), a1);
            w = bits_h2(__float_as_uint(e67.x));
            a0 = __hfma2(w, bits_h2(x6.x), a0); a1 = __hfma2(w, bits_h2(x6.y), a1);
            w = bits_h2(__float_as_uint(e67.z));
            a0 = __hfma2(w, bits_h2(x7.x), a0); a1 = __hfma2(w, bits_h2(x7.y), a1);

            float2 f0 = __half22float2(a0);
            float2 f1 = __half22float2(a1);
            acc.x += f0.x; acc.y += f0.y; acc.z += f1.x; acc.w += f1.y;
        }
        for (; j + 2 <= deg; j += 2) {      // fp32 tail
            float4 e01 = *(const float4*)(ep + j);
            uint2 x0 = GAT(e01.y);
            uint2 x1 = GAT(e01.w);
            accum_f(acc, __low2float(bits_h2(__float_as_uint(e01.x))), x0);
            accum_f(acc, __low2float(bits_h2(__float_as_uint(e01.z))), x1);
        }
        for (; j < deg; ++j) {
            float2 e = ep[j];
            uint2 x = GAT(e.y);
            accum_f(acc, __low2float(bits_h2(__float_as_uint(e.x))), x);
        }
        #undef GAT

        uint2 eh = *reinterpret_cast<const uint2*>(ego_in + (size_t)r * 32 + l * 2);
        g0 = __half22float2(bits_h2(eh.x));
        g1 = __half22float2(bits_h2(eh.y));
    }

    // A' row -> shared (fp16): [side | side*ego]
    {
        uint2 s, p;
        s.x = h2_bits(__floats2half2_rn(acc.x, acc.y));
        s.y = h2_bits(__floats2half2_rn(acc.z, acc.w));
        p.x = h2_bits(__floats2half2_rn(acc.x * g0.x, acc.y * g0.y));
        p.y = h2_bits(__floats2half2_rn(acc.z * g1.x, acc.w * g1.y));
        *reinterpret_cast<uint2*>(Ah + m * A_LD + l * 4)      = s;
        *reinterpret_cast<uint2*>(Ah + m * A_LD + 64 + l * 4) = p;
    }
    __syncthreads();

    // ---- MMA phase: C (32x64) = 2x4 tiles of 16x16; warps 0-7, one tile each
    wmma::fragment<wmma::accumulator, 16, 16, 16, float> cfrag;
    int tr = (warp >> 2) & 1, tc = warp & 3;
    if (warp < 8) {
        wmma::fill_fragment(cfrag, 0.f);
        #pragma unroll
        for (int kk = 0; kk < 8; ++kk) {
            wmma::fragment<wmma::matrix_a, 16, 16, 16, __half, wmma::row_major> a;
            wmma::fragment<wmma::matrix_b, 16, 16, 16, __half, wmma::row_major> b;
            wmma::load_matrix_sync(a, Ah + (tr * 16) * A_LD + kk * 16, A_LD);
            wmma::load_matrix_sync(b, Wsh + (kk * 16) * W_LD + tc * 16, W_LD);
            wmma::mma_sync(cfrag, a, b, cfrag);
        }
    }
    __syncthreads();   // all A reads done before Csh overwrites Ah
    if (warp < 8)
        wmma::store_matrix_sync(Csh + (tr * 16) * 64 + tc * 16, cfrag, 64,
                                wmma::mem_row_major);
    __syncthreads();

    // ---- Epilogue: 512 threads; thread -> (row ty, 4-col chunk tx)
    int ty = t >> 4, tx = t & 15;
    int c0i = tx * 4;

    float v[4];
    #pragma unroll
    for (int jj = 0; jj < 4; ++jj) {
        float x = Csh[ty * 64 + c0i + jj] + bsh[c0i + jj];
        x = (x > 0.f) ? x : 0.2f * x;
        v[jj] = x;
    }
    float sq = v[0]*v[0] + v[1]*v[1] + v[2]*v[2] + v[3]*v[3];
    #pragma unroll
    for (int off = 8; off; off >>= 1)
        sq += __shfl_xor_sync(0xffffffffu, sq, off, 16);
    float inv = 1.0f / fmaxf(sqrtf(sq), 1e-12f);

    int rr = row0 + ty;
    if (rr < NTOT) {
        if (write_ego) {
            uint2 h;
            h.x = h2_bits(__floats2half2_rn(v[0], v[1]));
            h.y = h2_bits(__floats2half2_rn(v[2], v[3]));
            *reinterpret_cast<uint2*>(ego_out + (size_t)rr * 32 + c0i / 2) = h;
        }
        float4 n = make_float4(v[0] * inv, v[1] * inv, v[2] * inv, v[3] * inv);
        *(float4*)(norm_out + (size_t)rr * 64 + c0i) = n;
    }
}

// ---------------------------------------------------------------------------
// 3) Final gather; slice 0 reconstructed from raw masked embeddings
// ---------------------------------------------------------------------------
__global__ void gather_kernel(const int* __restrict__ users,
                              const int* __restrict__ pos,
                              const int* __restrict__ neg,
                              const float4* __restrict__ ue,
                              const float4* __restrict__ ie,
                              const int* __restrict__ usz,
                              const int* __restrict__ isz,
                              float4* __restrict__ out)
{
    int i = blockIdx.x * blockDim.x + threadIdx.x;   // 3 * BATCH * 64 float4s
    if (i >= 3 * BATCH * 64) return;
    int which = i / (BATCH * 64);
    int rem   = i - which * (BATCH * 64);
    int b  = rem >> 6;
    int q  = rem & 63;
    int slice = q >> 4;
    int qq    = q & 15;

    int row;
    if      (which == 0) row = users[b];
    else if (which == 1) row = N_USERS + pos[b];
    else                 row = N_USERS + neg[b];

    if (slice == 0) {
        float4 v; int sz;
        if (row < N_USERS) { v = ue[(size_t)row * 16 + qq];              sz = usz[row]; }
        else               { v = ie[(size_t)(row - N_USERS) * 16 + qq];  sz = isz[row - N_USERS]; }
        int c0 = qq * 4;
        if (c0 + 0 >= sz) v.x = 0.f;
        if (c0 + 1 >= sz) v.y = 0.f;
        if (c0 + 2 >= sz) v.z = 0.f;
        if (c0 + 3 >= sz) v.w = 0.f;
        out[i] = v;
    } else {
        const float4* src = (const float4*)&g_outs[slice][0];
        out[i] = src[(size_t)row * 16 + qq];
    }
}

// ---------------------------------------------------------------------------
// Launcher (graph-capturable)
// ---------------------------------------------------------------------------
extern "C" void kernel_launch(void* const* d_in, const int* in_sizes, int n_in,
                              void* d_out, int out_size)
{
    const float* user_emb   = (const float*)d_in[0];
    const float* item_emb   = (const float*)d_in[1];
    const float* W_gc       = (const float*)d_in[2];
    const float* b_gc       = (const float*)d_in[3];
    const float* W_bi       = (const float*)d_in[4];
    const float* b_bi       = (const float*)d_in[5];
    const float* adj_vals   = (const float*)d_in[6];
    const int*   adj_rows   = (const int*)d_in[7];
    const int*   adj_cols   = (const int*)d_in[8];
    const int*   user_sizes = (const int*)d_in[9];
    const int*   item_sizes = (const int*)d_in[10];
    const int*   users      = (const int*)d_in[11];
    const int*   pos_items  = (const int*)d_in[12];
    const int*   neg_items  = (const int*)d_in[13];

    float *outs;
    int   *deg;
    __half *wh;
    float *bs;
    __half2 *egoh;
    cudaGetSymbolAddress((void**)&outs, g_outs);
    cudaGetSymbolAddress((void**)&deg,  g_deg);
    cudaGetSymbolAddress((void**)&wh,   g_wh);
    cudaGetSymbolAddress((void**)&bs,   g_bs);
    cudaGetSymbolAddress((void**)&egoh, g_egoh);

    const size_t SLICE  = (size_t)NTOT * EMB;
    const size_t HSLICE = (size_t)NTOT * (EMB / 2);

    cudaMemsetAsync(deg, 0, NTOT * sizeof(int), 0);

    preproc_kernel<<<SCAT_BLOCKS + INIT_BLOCKS + PREPW_BLOCKS, 256>>>(
        (const float4*)adj_vals, (const int4*)adj_rows, (const int4*)adj_cols,
        (const float4*)user_emb, (const float4*)item_emb,
        user_sizes, item_sizes,
        W_gc, W_bi, b_gc, b_bi);

    int cur = 0;
    for (int k = 0; k < NLAYERS; ++k) {
        layer_kernel<<<(NTOT + ROWS_PB - 1) / ROWS_PB, LTHREADS>>>(
            wh + (size_t)k * 128 * 64, bs + (size_t)k * 64,
            egoh + (size_t)cur * HSLICE, egoh + (size_t)(1 - cur) * HSLICE,
            outs + (size_t)(k + 1) * SLICE,
            (k + 1 < NLAYERS) ? 1 : 0);
        cur ^= 1;
    }

    gather_kernel<<<(3 * BATCH * 64 + 255) / 256, 256>>>(
        users, pos_items, neg_items,
        (const float4*)user_emb, (const float4*)item_emb,
        user_sizes, item_sizes, (float4*)d_out);
}